// round 10
// baseline (speedup 1.0000x reference)
#include <cuda_runtime.h>
#include <cuda_bf16.h>
#include <math.h>

// Problem constants
#define NB 16
#define FH 192
#define FW 192
#define NA 9
#define N_ANCH (FH*FW*NA)   // 331776
#define PRE 6000
#define POST 1000
#define CAND_CAP 8192
#define IOU_THR 0.7f
#define NTILES ((PRE + 31) / 32)   // 188
#define NBIN2 2050                 // 0: <0.5 | 1..2048: [0.5,1) | 2049: >=1.0
#define SEG_MAX 512

// ---------------- static scratch (zero-initialized at module load;
// k_nms re-zeroes the counters at the end of every run) ----------------
__device__ unsigned g_hist2[NB * NBIN2];
__device__ unsigned g_bcnt[NB * NBIN2];
__device__ unsigned g_segstart[NB * NBIN2];
__device__ unsigned g_tbin2[NB];
__device__ unsigned g_ticket;
__device__ unsigned long long g_cand[NB * CAND_CAP];
__device__ float4 g_boxes[NB * PRE];
__device__ float  g_area[NB * PRE];

__device__ __forceinline__ int score_bin(unsigned k) {
    if (k >= 0x3F800000u) return NBIN2 - 1;
    if (k >= 0x3F000000u) return 1 + (int)((k >> 12) & 0x7FFu);
    return 0;
}

// ---------------- K1: histogram (bin0 via registers) + fused threshold ----------------
// grid (81, NB) x 256
__global__ void k_histthresh(const float* __restrict__ labels) {
    __shared__ unsigned sh[NBIN2];
    int img = blockIdx.y, tid = threadIdx.x;
    for (int t = tid; t < NBIN2; t += 256) sh[t] = 0;
    __syncthreads();
    const float4* L = (const float4*)(labels + (size_t)img * N_ANCH);
    int base = blockIdx.x * 1024;
    unsigned c0 = 0;
    #pragma unroll
    for (int p = 0; p < 4; p++) {
        float4 v = L[base + p * 256 + tid];
        int b0 = score_bin(__float_as_uint(v.x));
        int b1 = score_bin(__float_as_uint(v.y));
        int b2 = score_bin(__float_as_uint(v.z));
        int b3 = score_bin(__float_as_uint(v.w));
        if (b0) atomicAdd(&sh[b0], 1u); else c0++;
        if (b1) atomicAdd(&sh[b1], 1u); else c0++;
        if (b2) atomicAdd(&sh[b2], 1u); else c0++;
        if (b3) atomicAdd(&sh[b3], 1u); else c0++;
    }
    #pragma unroll
    for (int o = 16; o > 0; o >>= 1) c0 += __shfl_down_sync(0xFFFFFFFFu, c0, o);
    if ((tid & 31) == 0 && c0) atomicAdd(&sh[0], c0);
    __syncthreads();
    for (int t = tid; t < NBIN2; t += 256) {
        unsigned c = sh[t];
        if (c) atomicAdd(&g_hist2[img * NBIN2 + t], c);
    }
    // ---- last block: threshold + segment offsets for all images ----
    __threadfence();
    __shared__ int isLast;
    __syncthreads();
    if (tid == 0) isLast = (atomicAdd(&g_ticket, 1u) == (unsigned)(gridDim.x * gridDim.y - 1));
    __syncthreads();
    if (!isLast) return;

    int w = tid >> 5, lane = tid & 31;
    for (int im = w; im < NB; im += 8) {
        const unsigned* h = g_hist2 + im * NBIN2;
        unsigned* ss = g_segstart + im * NBIN2;
        unsigned run = 0;
        int T = -1;
        for (int c = 0; c < (NBIN2 + 31) / 32 && T < 0; c++) {
            int b = (NBIN2 - 1) - (c * 32 + lane);
            unsigned cnt = (b >= 0) ? h[b] : 0u;
            unsigned inc = cnt;
            #pragma unroll
            for (int o = 1; o < 32; o <<= 1) {
                unsigned v = __shfl_up_sync(0xFFFFFFFFu, inc, o);
                if (lane >= o) inc += v;
            }
            if (b >= 0) ss[b] = run + inc - cnt;
            unsigned tot = __shfl_sync(0xFFFFFFFFu, inc, 31);
            unsigned hit = __ballot_sync(0xFFFFFFFFu, b >= 0 && (run + inc) >= PRE);
            if (hit) T = (NBIN2 - 1) - (c * 32 + (__ffs(hit) - 1));
            run += tot;
        }
        if (lane == 0) g_tbin2[im] = (T < 0) ? 0u : (unsigned)T;
    }
}

// ---------------- K2: compact + exact bin placement ----------------
__global__ void k_compact(const float* __restrict__ labels) {
    int img = blockIdx.y, tid = threadIdx.x;
    const float4* L = (const float4*)(labels + (size_t)img * N_ANCH);
    int tb = (int)g_tbin2[img];
    const unsigned* ss = g_segstart + img * NBIN2;
    unsigned* bc = g_bcnt + img * NBIN2;
    int base = blockIdx.x * 1024;
    #pragma unroll
    for (int p = 0; p < 4; p++) {
        int f4 = base + p * 256 + tid;
        float4 v = L[f4];
        float e[4] = {v.x, v.y, v.z, v.w};
        #pragma unroll
        for (int c = 0; c < 4; c++) {
            unsigned k = __float_as_uint(e[c]);
            int b = score_bin(k);
            if (b >= tb) {
                unsigned pos = ss[b] + atomicAdd(&bc[b], 1u);
                if (pos < CAND_CAP)
                    g_cand[img * CAND_CAP + pos] =
                        ((unsigned long long)(~k) << 32) | (unsigned)(f4 * 4 + c);
            }
        }
    }
}

// ---------------- K3: per-bin segment sort + fused decode ----------------
__global__ void k_segsort_decode(const float* __restrict__ deltas,
                                 const float* __restrict__ basea) {
    __shared__ unsigned long long s[8][SEG_MAX];
    int gw = blockIdx.x * 8 + (threadIdx.x >> 5);
    int lane = threadIdx.x & 31;
    int img = gw / NBIN2;
    int b = gw % NBIN2;
    if (img >= NB) return;
    if (b < (int)g_tbin2[img]) return;
    int L = (int)g_bcnt[img * NBIN2 + b];
    if (L < 1) return;
    if (L > SEG_MAX) L = SEG_MAX;
    unsigned start = g_segstart[img * NBIN2 + b];
    if (start >= PRE) return;                       // fully beyond top-K
    const unsigned long long* seg = g_cand + img * CAND_CAP + start;
    unsigned long long (&sw)[SEG_MAX] = s[threadIdx.x >> 5];

    int P2 = 32; while (P2 < L) P2 <<= 1;
    for (int t = lane; t < P2; t += 32)
        sw[t] = (t < L && start + t < CAND_CAP) ? seg[t] : 0xFFFFFFFFFFFFFFFFull;
    __syncwarp();
    if (L > 1) {
        for (int k = 2; k <= P2; k <<= 1) {
            for (int j = k >> 1; j > 0; j >>= 1) {
                for (int i = lane; i < P2; i += 32) {
                    int ixj = i ^ j;
                    if (ixj > i) {
                        bool up = ((i & k) == 0);
                        unsigned long long a = sw[i], bb = sw[ixj];
                        if ((a > bb) == up) { sw[i] = bb; sw[ixj] = a; }
                    }
                }
                __syncwarp();
            }
        }
    }
    // ---- decode entries with pos < PRE ----
    for (int t = lane; t < L; t += 32) {
        unsigned pos = start + t;
        if (pos >= PRE || pos >= CAND_CAP) continue;
        unsigned idx = (unsigned)sw[t];
        int a = idx % NA;
        int cell = idx / NA;
        int row = cell / FW;
        int col = cell % FW;
        float cy = ((float)row + 0.5f) / (float)FH;
        float cx = ((float)col + 0.5f) / (float)FW;
        float b0 = basea[a * 4 + 0], b1 = basea[a * 4 + 1];
        float b2 = basea[a * 4 + 2], b3 = basea[a * 4 + 3];
        float ay1 = fminf(fmaxf(cy + b0, 0.f), 1.f);
        float ax1 = fminf(fmaxf(cx + b1, 0.f), 1.f);
        float ay2 = fminf(fmaxf(cy + b2, 0.f), 1.f);
        float ax2 = fminf(fmaxf(cx + b3, 0.f), 1.f);
        float ah = ay2 - ay1, aw = ax2 - ax1;
        float acy = ay1 + 0.5f * ah, acx = ax1 + 0.5f * aw;
        const float4 d = *(const float4*)(deltas +
            ((size_t)((size_t)img * FH + row) * FW + col) * (NA * 4) + a * 4);
        float h = expf(d.z * 0.2f) * ah;
        float w = expf(d.w * 0.2f) * aw;
        float ccy = d.x * 0.1f * ah + acy;
        float ccx = d.y * 0.1f * aw + acx;
        float y1 = fminf(fmaxf(ccy - 0.5f * h, 0.f), 1.f);
        float x1 = fminf(fmaxf(ccx - 0.5f * w, 0.f), 1.f);
        float y2 = fminf(fmaxf(ccy + 0.5f * h, 0.f), 1.f);
        float x2 = fminf(fmaxf(ccx + 0.5f * w, 0.f), 1.f);
        g_boxes[img * PRE + pos] = make_float4(y1, x1, y2, x2);
        g_area[img * PRE + pos] = fmaxf(y2 - y1, 0.f) * fmaxf(x2 - x1, 0.f);
    }
}

// ---------------- K4: NMS with precomputed tile geometry + early-break Phase A ----------------
// Phase A: warp-per-candidate; lanes test 32 accepted per chunk, ballot-break
// on first kill. Accepted store ta = thr*(area+eps); candidate tc = thr*area.
// Test: 1.7*inter > ta + tc.
#define SM_SB   0
#define SM_SA   96000
#define SM_SUP  120000           // NTILES*32*4 = 24064
#define SM_ACCB 144064           // 16B aligned
#define SM_ACCA 160064
#define SM_NMS_TOTAL 164096

__global__ void __launch_bounds__(1024, 1) k_nms(float* __restrict__ out) {
    extern __shared__ char sm[];
    float4* sb = (float4*)(sm + SM_SB);
    float* sa = (float*)(sm + SM_SA);          // thr * area (candidate side)
    unsigned* sup_sm = (unsigned*)(sm + SM_SUP);
    float4* accb = (float4*)(sm + SM_ACCB);
    float* acca = (float*)(sm + SM_ACCA);      // thr * (area + eps) (accepted side)
    __shared__ unsigned char s_livearr[32];
    __shared__ int s_nacc, s_stop;

    int img = blockIdx.x, tid = threadIdx.x;
    int w = tid >> 5, lane = tid & 31;

    for (int j = tid; j < PRE; j += 1024) {
        sb[j] = g_boxes[img * PRE + j];
        sa[j] = IOU_THR * g_area[img * PRE + j];
    }
    if (tid == 0) { s_nacc = 0; s_stop = 0; }
    __syncthreads();

    // ---- precompute within-tile suppressor masks (all tiles, in parallel) ----
    for (int t = w; t < NTILES; t += 32) {
        int j = t * 32 + lane;
        float4 b; float taj;
        if (j < PRE) { b = sb[j]; taj = sa[j]; }
        else { b = make_float4(0.f, 0.f, 0.f, 0.f); taj = 0.f; }
        unsigned m = 0;
        #pragma unroll 1
        for (int kk = 0; kk < 32; kk++) {
            float ky1 = __shfl_sync(0xFFFFFFFFu, b.x, kk);
            float kx1 = __shfl_sync(0xFFFFFFFFu, b.y, kk);
            float ky2 = __shfl_sync(0xFFFFFFFFu, b.z, kk);
            float kx2 = __shfl_sync(0xFFFFFFFFu, b.w, kk);
            float tak = __shfl_sync(0xFFFFFFFFu, taj, kk);
            float y1 = fmaxf(b.x, ky1), x1 = fmaxf(b.y, kx1);
            float y2 = fminf(b.z, ky2), x2 = fminf(b.w, kx2);
            float inter = fmaxf(y2 - y1, 0.f) * fmaxf(x2 - x1, 0.f);
            // 1.7*inter > thr*(ai+eps) + thr*aj
            if (kk < lane && 1.7f * inter > (tak + IOU_THR * 1e-8f) + taj)
                m |= 1u << kk;
        }
        sup_sm[t * 32 + lane] = m;
    }
    __syncthreads();

    float4* out4 = (float4*)out + (size_t)img * POST;

    for (int tile = 0; tile < NTILES; tile++) {
        int tbase = tile * 32;
        int n0 = s_nacc;
        // ---- Phase A: warp w's candidate vs accepted (chunked, early break) ----
        int c = tbase + w;
        bool killed = false;
        if (c < PRE && n0 > 0) {
            float4 cb = sb[c];
            float tcj = sa[c];
            int nch = (n0 + 31) >> 5;
            for (int ch = 0; ch < nch; ch++) {
                int q = (ch << 5) + lane;
                bool k = false;
                if (q < n0) {
                    float4 b = accb[q];
                    float y1 = fmaxf(b.x, cb.x), x1 = fmaxf(b.y, cb.y);
                    float y2 = fminf(b.z, cb.z), x2 = fminf(b.w, cb.w);
                    float inter = fmaxf(y2 - y1, 0.f) * fmaxf(x2 - x1, 0.f);
                    k = (1.7f * inter > acca[q] + tcj);
                }
                if (__ballot_sync(0xFFFFFFFFu, k)) { killed = true; break; }
            }
        }
        if (lane == 0) s_livearr[w] = (c < PRE) && !killed;
        __syncthreads();
        // ---- Phase B: warp 0 resolves the tile with the precomputed mask ----
        if (w == 0) {
            bool lv = s_livearr[lane] != 0;
            unsigned m = sup_sm[tbase + lane];
            unsigned rem = __ballot_sync(0xFFFFFFFFu, lv);
            int room = POST - n0;
            unsigned acc = 0;
            int na = 0;
            while (rem && na < room) {
                int j2 = __ffs(rem) - 1;
                acc |= 1u << j2;
                na++;
                unsigned dead = __ballot_sync(0xFFFFFFFFu, (m >> j2) & 1u);
                rem &= ~dead;
                rem &= ~(1u << j2);
            }
            if ((acc >> lane) & 1u) {
                int j = tbase + lane;
                int ord = __popc(acc & ((1u << lane) - 1u));
                float4 b = sb[j];
                accb[n0 + ord] = b;
                acca[n0 + ord] = sa[j] + IOU_THR * 1e-8f;
                out4[n0 + ord] = b;
            }
            if (lane == 0) {
                s_nacc = n0 + na;
                if (n0 + na >= POST) s_stop = 1;
            }
        }
        __syncthreads();
        if (s_stop) break;
    }

    // zero-pad remaining rows
    for (int r = s_nacc + tid; r < POST; r += 1024)
        out4[r] = make_float4(0.f, 0.f, 0.f, 0.f);

    // ---- restore counters for the next run / graph replay ----
    unsigned* h = g_hist2 + img * NBIN2;
    unsigned* bc = g_bcnt + img * NBIN2;
    for (int t = tid; t < NBIN2; t += 1024) { h[t] = 0; bc[t] = 0; }
    if (img == 0 && tid == 0) g_ticket = 0;
}

// ---------------- launch (4 kernels; #4 = k_nms -> ncu slot) ----------------
extern "C" void kernel_launch(void* const* d_in, const int* in_sizes, int n_in,
                              void* d_out, int out_size) {
    const float* deltas = (const float*)d_in[0];
    const float* labels = (const float*)d_in[1];
    const float* base   = (const float*)d_in[2];
    float* out = (float*)d_out;

    cudaFuncSetAttribute(k_nms, cudaFuncAttributeMaxDynamicSharedMemorySize, SM_NMS_TOTAL);

    dim3 gq(81, NB);
    k_histthresh<<<gq, 256>>>(labels);                             // 1
    k_compact<<<gq, 256>>>(labels);                                // 2
    k_segsort_decode<<<(NB * NBIN2 + 7) / 8, 256>>>(deltas, base); // 3
    k_nms<<<NB, 1024, SM_NMS_TOTAL>>>(out);                        // 4  <- ncu slot
}